// round 17
// baseline (speedup 1.0000x reference)
#include <cuda_runtime.h>
#include <cuda_bf16.h>
#include <math.h>

// ---------------- problem constants ----------------
#define BATCH 128
#define SPAT  121          // H*W = d_spectral (dg)
#define SPP   128          // padded row stride for u/delta
#define DM    128          // d_model
#define DI    256          // d_inner = scan length L
#define NST   16           // d_state
#define RTK   8            // dt_rank
#define C40   40           // dt_rank + 2*NST per direction
#define C80   80           // merged both directions
#define ROWS  (BATCH*SPAT) // 15488
#define BL    (BATCH*DI)   // 32768 rows for per-(b,l) GEMMs

#define NCHUNK 4
#define LCHUNK (DI/NCHUNK) // 64

// scan dynamic smem (floats)
#define SH_B  0
#define SH_C  4096
#define SH_H  8192
#define SH_S  16904
#define SCAN_SMEM_FLOATS (SH_S + 512)
#define SCAN_SMEM_BYTES  (SCAN_SMEM_FLOATS * 4)

// gemm dynamic smem: 3 stages x (A,B) x 128 x SPAD floats
#define SPAD 36
#define GT_TILE (128 * SPAD)
#define GT_SMEM_BYTES (3 * 2 * GT_TILE * 4)   // 110592

// ---------------- scratch (device globals; no allocation allowed) ----------------
__device__ float g_xz   [ROWS*512];          // in_proj output [b*121+s][512]
__device__ float g_u    [(size_t)BL*SPP];    // conv+silu out, [b][l][dg] (pad 128)
__device__ float g_xw   [C80*SPP];           // x_proj_w zero-padded to [80][128]
__device__ float g_xdbl2[(size_t)BL*C80];    // merged x_dbl   [b*256+l][80]
__device__ float4 g_dd  [2ull*BL*SPP];       // (d, d*u, D*u, 0) per [k][b,l][dg]
__device__ float g_ys   [2ull*BL*SPAT];      // scan out       [k][b*256+l][dg]
__device__ float g_ygT  [ROWS*DI];           // LN*gelu(z)     [b*121+dg][l]

// ---------------- packed f32x2 helpers (Blackwell FFMA2 path) ----------------
typedef unsigned long long ull;
__device__ __forceinline__ ull pk2(float lo, float hi) {
    ull r; asm("mov.b64 %0, {%1, %2};" : "=l"(r) : "f"(lo), "f"(hi)); return r;
}
__device__ __forceinline__ float2 upk2(ull v) {
    float2 f; asm("mov.b64 {%0, %1}, %2;" : "=f"(f.x), "=f"(f.y) : "l"(v)); return f;
}
__device__ __forceinline__ ull fma2(ull a, ull b, ull c) {
    ull d; asm("fma.rn.f32x2 %0, %1, %2, %3;" : "=l"(d) : "l"(a), "l"(b), "l"(c)); return d;
}
__device__ __forceinline__ ull mul2(ull a, ull b) {
    ull d; asm("mul.rn.f32x2 %0, %1, %2;" : "=l"(d) : "l"(a), "l"(b)); return d;
}

// fast softplus: max(x,0) + log(1+exp(-|x|)), MUFU-based
__device__ __forceinline__ float softplus_fast(float x) {
    return fmaxf(x, 0.f) + __logf(1.f + __expf(-fabsf(x)));
}

// ---------------- tf32 tensor-core GEMM (3-stage cp.async pipeline) ----------------
__device__ __forceinline__ unsigned f2tf32(float v) {
    unsigned r;
    asm("cvt.rna.tf32.f32 %0, %1;" : "=r"(r) : "f"(v));
    return r;
}

__device__ __forceinline__ void mma_tf32_c(float (&d)[4], const unsigned (&a)[4],
                                           const unsigned (&b)[2]) {
    asm volatile(
        "mma.sync.aligned.m16n8k8.row.col.f32.tf32.tf32.f32 "
        "{%0,%1,%2,%3}, {%4,%5,%6,%7}, {%8,%9}, {%0,%1,%2,%3};\n"
        : "+f"(d[0]), "+f"(d[1]), "+f"(d[2]), "+f"(d[3])
        : "r"(a[0]), "r"(a[1]), "r"(a[2]), "r"(a[3]), "r"(b[0]), "r"(b[1]));
}

__device__ __forceinline__ void gt_load_tile(
    const float* __restrict__ A, const float* __restrict__ W,
    float* Af, float* Bf,
    int rowBase, int colBase, int N, int k0, int lda, int ldb, int t)
{
#pragma unroll
    for (int j = 0; j < 4; j++) {
        int i  = t + j * 256;            // 0..1023
        int r  = i >> 3;
        int c4 = (i & 7) << 2;
        unsigned da = (unsigned)__cvta_generic_to_shared(&Af[r * SPAD + c4]);
        const float* as = &A[(size_t)(rowBase + r) * lda + k0 + c4];
        asm volatile("cp.async.ca.shared.global [%0], [%1], 16;" :: "r"(da), "l"(as));
        unsigned db = (unsigned)__cvta_generic_to_shared(&Bf[r * SPAD + c4]);
        bool ok = (colBase + r) < N;
        const float* ws = &W[(size_t)(colBase + (ok ? r : 0)) * ldb + k0 + c4];
        if (ok)
            asm volatile("cp.async.ca.shared.global [%0], [%1], 16;" :: "r"(db), "l"(ws));
        else
            asm volatile("cp.async.ca.shared.global [%0], [%1], 16, 0;" :: "r"(db), "l"(ws));
    }
    asm volatile("cp.async.commit_group;");
}

__global__ void __launch_bounds__(256) gemm_tc(
    const float* __restrict__ A, const float* __restrict__ W,
    float* __restrict__ C, int N, int K, int lda, int ldb, int ldc)
{
    extern __shared__ float gsm[];

    const int t    = threadIdx.x;
    const int wid  = t >> 5, lane = t & 31;
    const int g    = lane >> 2, tig = lane & 3;
    const int wm   = wid >> 1, wn = wid & 1;
    const int rowBase = blockIdx.x * 128;
    const int colBase = blockIdx.y * 128;

    float acc[2][8][4];
#pragma unroll
    for (int mt = 0; mt < 2; mt++)
#pragma unroll
        for (int nt = 0; nt < 8; nt++)
#pragma unroll
            for (int q = 0; q < 4; q++) acc[mt][nt][q] = 0.f;

    const int nk = K >> 5;   // K % 32 == 0 at all call sites

    // prefetch tiles 0,1
    gt_load_tile(A, W, gsm, gsm + GT_TILE, rowBase, colBase, N, 0, lda, ldb, t);
    if (nk > 1) {
        float* s1 = gsm + 2 * GT_TILE;
        gt_load_tile(A, W, s1, s1 + GT_TILE, rowBase, colBase, N, 32, lda, ldb, t);
    }

    for (int kt = 0; kt < nk; kt++) {
        const int st = kt % 3;
        float* Af = gsm + st * 2 * GT_TILE;
        float* Bf = Af + GT_TILE;

        // everyone finished compute(kt-1) -> stage (kt+2)%3 is free to overwrite
        __syncthreads();
        if (kt + 2 < nk) {
            float* s2 = gsm + ((kt + 2) % 3) * 2 * GT_TILE;
            gt_load_tile(A, W, s2, s2 + GT_TILE,
                         rowBase, colBase, N, (kt + 2) * 32, lda, ldb, t);
            asm volatile("cp.async.wait_group 2;");
        } else if (kt + 1 < nk) {
            asm volatile("cp.async.wait_group 1;");
        } else {
            asm volatile("cp.async.wait_group 0;");
        }
        __syncthreads();

#pragma unroll
        for (int ks = 0; ks < 4; ks++) {
            const int kk = ks * 8;
            unsigned af[2][4], bf[8][2];
#pragma unroll
            for (int mt = 0; mt < 2; mt++) {
                int row = wm * 32 + mt * 16 + g;
                af[mt][0] = f2tf32(Af[ row      * SPAD + kk + tig]);
                af[mt][1] = f2tf32(Af[(row + 8) * SPAD + kk + tig]);
                af[mt][2] = f2tf32(Af[ row      * SPAD + kk + tig + 4]);
                af[mt][3] = f2tf32(Af[(row + 8) * SPAD + kk + tig + 4]);
            }
#pragma unroll
            for (int nt = 0; nt < 8; nt++) {
                int col = wn * 64 + nt * 8 + g;
                bf[nt][0] = f2tf32(Bf[col * SPAD + kk + tig]);
                bf[nt][1] = f2tf32(Bf[col * SPAD + kk + tig + 4]);
            }
#pragma unroll
            for (int mt = 0; mt < 2; mt++)
#pragma unroll
                for (int nt = 0; nt < 8; nt++)
                    mma_tf32_c(acc[mt][nt], af[mt], bf[nt]);
        }
    }

#pragma unroll
    for (int mt = 0; mt < 2; mt++) {
#pragma unroll
        for (int nt = 0; nt < 8; nt++) {
            int row0 = rowBase + wm * 32 + mt * 16 + g;
            int col0 = colBase + wn * 64 + nt * 8 + 2 * tig;
            if (col0 < N) {
                C[(size_t)row0 * ldc + col0]           = acc[mt][nt][0];
                C[(size_t)(row0 + 8) * ldc + col0]     = acc[mt][nt][2];
            }
            if (col0 + 1 < N) {
                C[(size_t)row0 * ldc + col0 + 1]       = acc[mt][nt][1];
                C[(size_t)(row0 + 8) * ldc + col0 + 1] = acc[mt][nt][3];
            }
        }
    }
}

// ---------------- pack x_proj_w [80][121] -> zero-padded [80][128] ----------------
__global__ void __launch_bounds__(256) pack_w_kernel(
    const float* __restrict__ x_proj_w, float* __restrict__ xw)
{
    int i = blockIdx.x * 256 + threadIdx.x;
    if (i >= C80 * SPP) return;
    int r = i >> 7, c = i & 127;
    xw[i] = (c < SPAT) ? x_proj_w[r * SPAT + c] : 0.f;
}

// ---------------- depthwise 3x3 conv + SiLU, xz[:, :256] -> u[b][l][dg](pad128) ----------------
__global__ void __launch_bounds__(256) conv_kernel(
    const float* __restrict__ xz, const float* __restrict__ conv_w,
    const float* __restrict__ conv_b, float* __restrict__ u)
{
    __shared__ float s_in[SPAT * 65];
    int ct = blockIdx.x;
    int b  = blockIdx.y;
    int t  = threadIdx.x;

    for (int idx = t; idx < SPAT * 64; idx += 256) {
        int s = idx >> 6, c = idx & 63;
        s_in[s * 65 + c] = xz[((size_t)b * SPAT + s) * 512 + ct * 64 + c];
    }
    __syncthreads();

    size_t base = ((size_t)b * DI + ct * 64) * SPP;
    for (int idx = t; idx < 64 * SPP; idx += 256) {
        int c = idx >> 7;
        int s = idx & 127;
        float sv = 0.f;
        if (s < SPAT) {
            int i = s / 11, j = s - i * 11;
            int ch = ct * 64 + c;
            float acc = conv_b[ch];
#pragma unroll
            for (int ti = 0; ti < 3; ti++) {
                int ii = i + ti - 1;
                if ((unsigned)ii < 11u) {
#pragma unroll
                    for (int tj = 0; tj < 3; tj++) {
                        int jj = j + tj - 1;
                        if ((unsigned)jj < 11u)
                            acc += s_in[(ii * 11 + jj) * 65 + c] * conv_w[ch * 9 + ti * 3 + tj];
                    }
                }
            }
            sv = acc / (1.f + __expf(-acc));
        }
        u[base + idx] = sv;
    }
}

// ---------------- delta precompute -> float4 (d, d*u, D*u, 0) ----------------
__global__ void __launch_bounds__(512) delta_kernel(
    const float* __restrict__ xdbl2, const float* __restrict__ u,
    const float* __restrict__ dt_proj_w, const float* __restrict__ dt_proj_b,
    const float* __restrict__ Ds, float4* __restrict__ dd)
{
    __shared__ float sdt[DI][RTK];

    const int b = blockIdx.x;
    const int k = blockIdx.y;
    const int tid = threadIdx.x;
    const int lgrp = tid >> 7;
    const int dg = tid & 127;
    const bool act = dg < SPAT;

    const float* xd = xdbl2 + ((size_t)b * DI) * C80 + k * C40;
    for (int idx = tid; idx < DI * RTK; idx += 512) {
        int l = idx >> 3, r = idx & 7;
        sdt[l][r] = __ldg(&xd[(size_t)l * C80 + r]);
    }

    float w8[RTK];
    float bias = 0.f, Dv = 0.f;
    if (act) {
        const float* wrow = dt_proj_w + ((size_t)k * SPAT + dg) * RTK;
#pragma unroll
        for (int r = 0; r < RTK; r++) w8[r] = wrow[r];
        bias = dt_proj_b[k * SPAT + dg];
        Dv = Ds[k * SPAT + dg];
    }
    __syncthreads();

    if (!act) return;
    const float* uptr = u + ((size_t)b * DI) * SPP + dg;
    float4* dout = dd + ((size_t)k * BL + (size_t)b * DI) * SPP + dg;
    for (int l = lgrp; l < DI; l += 4) {
        float dr = bias;
#pragma unroll
        for (int r = 0; r < RTK; r++) dr = fmaf(w8[r], sdt[l][r], dr);
        float d  = softplus_fast(dr);
        float uv = uptr[(size_t)l * SPP];
        dout[(size_t)l * SPP] = make_float4(d, d * uv, Dv * uv, 0.f);
    }
}

// ---------------- chunk-parallel selective scan (f32x2 + single LDG.128/step) ----------------
__global__ void __launch_bounds__(512, 2) scan_kernel(
    const float* __restrict__ xdbl2, const float4* __restrict__ dd,
    const float* __restrict__ A_logs, float* __restrict__ ys)
{
    extern __shared__ float sm[];
    float* sB = sm + SH_B;
    float* sC = sm + SH_C;
    float* sH = sm + SH_H;
    float* sS = sm + SH_S;

    const int b   = blockIdx.x;
    const int k   = blockIdx.y;
    const int tid = threadIdx.x;
    const int c   = tid >> 7;
    const int dg  = tid & 127;
    const bool act = dg < SPAT;

    const float* xd = xdbl2 + ((size_t)b * DI) * C80 + k * C40 + RTK;
    for (int idx = tid; idx < DI * 32; idx += 512) {
        int l = idx >> 5, cc = idx & 31;
        float v = __ldg(&xd[(size_t)l * C80 + cc]);
        if (cc < NST) sB[l * NST + cc] = v;
        else          sC[l * NST + (cc - NST)] = v;
    }

    float a1 = 0.f;
    bool geo = false;
    const float* arow = A_logs + ((size_t)k * SPAT + (act ? dg : 0)) * NST;
    if (act) {
        a1 = -expf(arow[0]);
        geo = true;
#pragma unroll
        for (int n = 0; n < NST; n++) {
            float an = -expf(arow[n]);
            float tgt = (float)(n + 1) * a1;
            if (fabsf(an - tgt) > 1e-5f * (float)(n + 1) * fabsf(a1)) geo = false;
        }
    }
    __syncthreads();

    const float4* dptr = dd + ((size_t)k * BL + (size_t)b * DI) * SPP + dg;
    const int l_beg = c * LCHUNK;
    const int l_end = l_beg + LCHUNK;

    // ---- Phase A: local scan, chunks 0..2 ----
    if (act && c < NCHUNK - 1) {
        ull hh2[8];
#pragma unroll
        for (int j = 0; j < 8; j++) hh2[j] = pk2(0.f, 0.f);
        float S = 0.f;
        if (geo) {
            float4 vc = dptr[(size_t)l_beg * SPP];
            for (int l = l_beg; l < l_end; l++) {
                float4 v = vc;
                if (l + 1 < l_end) vc = dptr[(size_t)(l + 1) * SPP];
                S += v.x;
                float q1 = __expf(v.x * a1);
                float q2 = q1 * q1;
                ull e2 = pk2(q1, q2), qq = pk2(q2, q2), du2 = pk2(v.y, v.y);
                const float4* B4 = (const float4*)&sB[l * NST];
#pragma unroll
                for (int jj = 0; jj < 4; jj++) {
                    float4 bb = B4[jj];
                    hh2[2*jj]   = fma2(e2, hh2[2*jj],   mul2(du2, pk2(bb.x, bb.y)));
                    e2 = mul2(e2, qq);
                    hh2[2*jj+1] = fma2(e2, hh2[2*jj+1], mul2(du2, pk2(bb.z, bb.w)));
                    e2 = mul2(e2, qq);
                }
            }
        } else {
            float hs[NST];
#pragma unroll
            for (int n = 0; n < NST; n++) hs[n] = 0.f;
            for (int l = l_beg; l < l_end; l++) {
                float4 v = dptr[(size_t)l * SPP];
                S += v.x;
#pragma unroll
                for (int n = 0; n < NST; n++) {
                    float e = __expf(v.x * __ldg(&arow[n]));
                    hs[n] = e * hs[n] + v.y * sB[l * NST + n];
                }
            }
#pragma unroll
            for (int j = 0; j < 8; j++) hh2[j] = pk2(hs[2*j], hs[2*j+1]);
        }
        float* hrow = &sH[(size_t)(c * SPAT + dg) * 18];
#pragma unroll
        for (int j = 0; j < 8; j++) {
            float2 hv = upk2(hh2[j]);
            hrow[2*j] = hv.x; hrow[2*j+1] = hv.y;
        }
        sS[c * 128 + dg] = S;
    }
    __syncthreads();

    // ---- Combine: prefix over chunk ends ----
    if (act && c == 0) {
        for (int cc = 1; cc < NCHUNK - 1; cc++) {
            float Sc = sS[cc * 128 + dg];
            float* cur = &sH[(size_t)(cc * SPAT + dg) * 18];
            float* prv = &sH[(size_t)((cc - 1) * SPAT + dg) * 18];
            if (geo) {
                float p1 = __expf(Sc * a1);
                float e = 1.f;
#pragma unroll
                for (int n = 0; n < NST; n++) {
                    e *= p1;
                    cur[n] += e * prv[n];
                }
            } else {
#pragma unroll
                for (int n = 0; n < NST; n++) {
                    float e = __expf(Sc * __ldg(&arow[n]));
                    cur[n] += e * prv[n];
                }
            }
        }
    }
    __syncthreads();

    // ---- Phase C: full scan seeded with true h0 ----
    if (act) {
        ull hh2[8];
        if (c == 0) {
#pragma unroll
            for (int j = 0; j < 8; j++) hh2[j] = pk2(0.f, 0.f);
        } else {
            const float* hrow = &sH[(size_t)((c - 1) * SPAT + dg) * 18];
#pragma unroll
            for (int j = 0; j < 8; j++) hh2[j] = pk2(hrow[2*j], hrow[2*j+1]);
        }
        float* yptr = ys + ((size_t)k * BL + (size_t)b * DI) * SPAT + dg;
        if (geo) {
            float4 vc = dptr[(size_t)l_beg * SPP];
            for (int l = l_beg; l < l_end; l++) {
                float4 v = vc;
                if (l + 1 < l_end) vc = dptr[(size_t)(l + 1) * SPP];
                float q1 = __expf(v.x * a1);
                float q2 = q1 * q1;
                ull e2 = pk2(q1, q2), qq = pk2(q2, q2), du2 = pk2(v.y, v.y);
                ull yacc = pk2(0.f, 0.f);
                const float4* B4 = (const float4*)&sB[l * NST];
                const float4* C4 = (const float4*)&sC[l * NST];
#pragma unroll
                for (int jj = 0; jj < 4; jj++) {
                    float4 bb = B4[jj];
                    float4 cv = C4[jj];
                    hh2[2*jj]   = fma2(e2, hh2[2*jj],   mul2(du2, pk2(bb.x, bb.y)));
                    yacc        = fma2(hh2[2*jj], pk2(cv.x, cv.y), yacc);
                    e2 = mul2(e2, qq);
                    hh2[2*jj+1] = fma2(e2, hh2[2*jj+1], mul2(du2, pk2(bb.z, bb.w)));
                    yacc        = fma2(hh2[2*jj+1], pk2(cv.z, cv.w), yacc);
                    e2 = mul2(e2, qq);
                }
                float2 yv = upk2(yacc);
                yptr[(size_t)l * SPAT] = yv.x + yv.y + v.z;
            }
        } else {
            float hs[NST];
#pragma unroll
            for (int j = 0; j < 8; j++) {
                float2 hv = upk2(hh2[j]);
                hs[2*j] = hv.x; hs[2*j+1] = hv.y;
            }
            for (int l = l_beg; l < l_end; l++) {
                float4 v = dptr[(size_t)l * SPP];
                float y = 0.f;
#pragma unroll
                for (int n = 0; n < NST; n++) {
                    float e = __expf(v.x * __ldg(&arow[n]));
                    hs[n] = e * hs[n] + v.y * sB[l * NST + n];
                    y += hs[n] * sC[l * NST + n];
                }
                yptr[(size_t)l * SPAT] = y + v.z;
            }
        }
    }
}

// ---------------- combine dirs + LayerNorm(dg) + gelu(z) gate; write [b][dg][l] ----------------
__global__ void __launch_bounds__(256) ln_kernel(
    const float* __restrict__ ys, const float* __restrict__ xz,
    const float* __restrict__ ln_g, const float* __restrict__ ln_b,
    float* __restrict__ ygT)
{
    __shared__ float tY[64 * 129];
    __shared__ float s_mu[64], s_rs[64];

    int lt = blockIdx.x;
    int b  = blockIdx.y;
    int t  = threadIdx.x;

    const float* ysA = ys + ((size_t)b * DI + lt * 64) * SPAT;
    const float* ysB = ys + (size_t)BL * SPAT + (size_t)b * DI * SPAT;

    for (int idx = t; idx < 64 * SPAT; idx += 256) {
        int l = idx / SPAT, dg = idx - l * SPAT;
        int gl = lt * 64 + l;
        float v = ysA[(size_t)l * SPAT + dg] + ysB[(size_t)(255 - gl) * SPAT + dg];
        tY[l * 129 + dg] = v;
    }
    __syncthreads();

    int w = t >> 5, lane = t & 31;
    for (int l = w * 8; l < w * 8 + 8; l++) {
        float s1 = 0.f, s2 = 0.f;
        for (int dg = lane; dg < SPAT; dg += 32) {
            float v = tY[l * 129 + dg];
            s1 += v; s2 += v * v;
        }
#pragma unroll
        for (int off = 16; off > 0; off >>= 1) {
            s1 += __shfl_xor_sync(0xffffffffu, s1, off);
            s2 += __shfl_xor_sync(0xffffffffu, s2, off);
        }
        if (lane == 0) {
            float mu = s1 * (1.f / SPAT);
            float var = s2 * (1.f / SPAT) - mu * mu;
            s_mu[l] = mu;
            s_rs[l] = rsqrtf(var + 1e-5f);
        }
    }
    __syncthreads();

    for (int idx = t; idx < SPAT * 64; idx += 256) {
        int dg = idx >> 6, l = idx & 63;
        int gl = lt * 64 + l;
        float v = (tY[l * 129 + dg] - s_mu[l]) * s_rs[l] * ln_g[dg] + ln_b[dg];
        float zv = xz[((size_t)b * SPAT + dg) * 512 + 256 + gl];
        float gz = 0.5f * zv * (1.f + erff(zv * 0.7071067811865475f));
        ygT[((size_t)b * SPAT + dg) * DI + gl] = v * gz;
    }
}

// ---------------- launcher ----------------
extern "C" void kernel_launch(void* const* d_in, const int* in_sizes, int n_in,
                              void* d_out, int out_size)
{
    const float* x         = (const float*)d_in[0];
    const float* in_proj_w = (const float*)d_in[1];
    const float* conv_w    = (const float*)d_in[2];
    const float* conv_b    = (const float*)d_in[3];
    const float* x_proj_w  = (const float*)d_in[4];
    const float* dt_proj_w = (const float*)d_in[5];
    const float* dt_proj_b = (const float*)d_in[6];
    const float* A_logs    = (const float*)d_in[7];
    const float* Ds        = (const float*)d_in[8];
    const float* ln_g      = (const float*)d_in[9];
    const float* ln_b      = (const float*)d_in[10];
    const float* out_proj_w= (const float*)d_in[11];
    float* out = (float*)d_out;

    float *p_xz, *p_u, *p_xw, *p_xdbl2, *p_ys, *p_ygT;
    float4 *p_dd;
    cudaGetSymbolAddress((void**)&p_xz,    g_xz);
    cudaGetSymbolAddress((void**)&p_u,     g_u);
    cudaGetSymbolAddress((void**)&p_xw,    g_xw);
    cudaGetSymbolAddress((void**)&p_xdbl2, g_xdbl2);
    cudaGetSymbolAddress((void**)&p_dd,    g_dd);
    cudaGetSymbolAddress((void**)&p_ys,    g_ys);
    cudaGetSymbolAddress((void**)&p_ygT,   g_ygT);

    cudaFuncSetAttribute(scan_kernel,
                         cudaFuncAttributeMaxDynamicSharedMemorySize,
                         SCAN_SMEM_BYTES);
    cudaFuncSetAttribute(gemm_tc,
                         cudaFuncAttributeMaxDynamicSharedMemorySize,
                         GT_SMEM_BYTES);

    // K0: pack x_proj_w into padded [80][128]
    pack_w_kernel<<<(C80 * SPP + 255) / 256, 256>>>(x_proj_w, p_xw);

    // K1: xz = x @ in_proj_w.T   [15488,128] x [512,128]^T
    gemm_tc<<<dim3(ROWS / 128, 4), 256, GT_SMEM_BYTES>>>(
        x, in_proj_w, p_xz, 512, DM, DM, DM, 512);

    // K2: depthwise conv + SiLU -> u[b][l][dg] (stride 128, zero-padded)
    conv_kernel<<<dim3(4, BATCH), 256>>>(p_xz, conv_w, conv_b, p_u);

    // K3: merged x_dbl: [32768,128pad] x [80,128pad]^T -> [32768,80]
    gemm_tc<<<dim3(BL / 128, 1), 256, GT_SMEM_BYTES>>>(
        p_u, p_xw, p_xdbl2, C80, SPP, SPP, SPP, C80);

    // K3b: dd = (softplus(dt-proj), d*u, D*u, 0)
    delta_kernel<<<dim3(BATCH, 2), 512>>>(
        p_xdbl2, p_u, dt_proj_w, dt_proj_b, Ds, p_dd);

    // K4: chunk-parallel selective scan (f32x2, one LDG.128 per step)
    scan_kernel<<<dim3(BATCH, 2), 512, SCAN_SMEM_BYTES>>>(
        p_xdbl2, p_dd, A_logs, p_ys);

    // K5: combine directions + LN + gelu(z) gate -> ygT[b*121+dg][l]
    ln_kernel<<<dim3(4, BATCH), 256>>>(p_ys, p_xz, ln_g, ln_b, p_ygT);

    // K6: out = ygT @ out_proj_w.T   [15488,256] x [128,256]^T
    gemm_tc<<<dim3(ROWS / 128, 1), 256, GT_SMEM_BYTES>>>(
        p_ygT, out_proj_w, out, DM, DI, DI, DI, DM);
}